// round 8
// baseline (speedup 1.0000x reference)
#include <cuda_runtime.h>
#include <cuda_bf16.h>
#include <cstdint>

// Problem constants
#define BB 32
#define LL 1024
#define EE 256
#define HH 256
#define TT 8192
#define KD 768                  // 3*256 im2col contraction
#define MM (BB*LL)              // 32768 rows
#define OUT_OFF (BB*TT*EE)      // duration follows output
#define NCH 24                  // K chunks of 32
#define CHK 32
#define NT 512                  // threads per CTA (16 warps)

// Weight blocks: per conv [NCH][2(hi/lo)][32 k][264 n] bf16 (264 = 256 + pad)
#define BROW 264
#define BCH  (2*32*BROW)        // 16896 elems / chunk

__device__ float g_H1[MM*HH];
__device__ __align__(16) __nv_bfloat16 g_B1[NCH*BCH];
__device__ __align__(16) __nv_bfloat16 g_B2[NCH*BCH];
__device__ int g_idx[BB*TT];

// SMEM layout (dynamic): params [0,4096), 3 stages from 4096; epilogue reuses stages
#define SM_STAGE 4096
#define A_HI 0
#define A_LO 10240
#define B_HI 20480
#define B_LO (20480 + 16896)
#define STAGE_SZ 54272
#define ASTR 80                 // A row stride bytes (32 bf16 + pad)
#define BSTR 528                // B row stride bytes (264 bf16)
#define EPI_STRIDE 264          // epilogue fp32 tile row stride (floats)
#define SMEM_BYTES (4096 + 3*STAGE_SZ)   // 166912

__device__ __forceinline__ void ldsm4(uint32_t* r, uint32_t a) {
    asm volatile("ldmatrix.sync.aligned.m8n8.x4.shared.b16 {%0,%1,%2,%3}, [%4];"
        : "=r"(r[0]), "=r"(r[1]), "=r"(r[2]), "=r"(r[3]) : "r"(a));
}
__device__ __forceinline__ void ldsm4t(uint32_t* r, uint32_t a) {
    asm volatile("ldmatrix.sync.aligned.m8n8.x4.trans.shared.b16 {%0,%1,%2,%3}, [%4];"
        : "=r"(r[0]), "=r"(r[1]), "=r"(r[2]), "=r"(r[3]) : "r"(a));
}
__device__ __forceinline__ void mma_bf16(float* d, const uint32_t* a, const uint32_t* b) {
    asm volatile(
        "mma.sync.aligned.m16n8k16.row.col.f32.bf16.bf16.f32 "
        "{%0,%1,%2,%3}, {%4,%5,%6,%7}, {%8,%9}, {%0,%1,%2,%3};"
        : "+f"(d[0]), "+f"(d[1]), "+f"(d[2]), "+f"(d[3])
        : "r"(a[0]), "r"(a[1]), "r"(a[2]), "r"(a[3]), "r"(b[0]), "r"(b[1]));
}
__device__ __forceinline__ uint32_t pack_bf2(float x, float y) {
    __nv_bfloat16 hx = __float2bfloat16(x), hy = __float2bfloat16(y);
    return (uint32_t)__bfloat16_as_ushort(hx) |
           ((uint32_t)__bfloat16_as_ushort(hy) << 16);
}

// ---------------------------------------------------------------------------
// Weight prep: [H,E,K] fp32 -> bf16 hi/lo in [chunk][2][k'][n=h] padded rows
// ---------------------------------------------------------------------------
__global__ void prep_weights(const float* __restrict__ c1w,
                             const float* __restrict__ c2w) {
    int i = blockIdx.x * blockDim.x + threadIdx.x;
    if (i >= HH * KD) return;
    int h = i / KD, kk = i % KD;
    int k = kk / EE, e = kk % EE;
    int c = kk >> 5, kp = kk & 31;
    size_t dhi = ((size_t)(c * 2 + 0) * 32 + kp) * BROW + h;
    size_t dlo = ((size_t)(c * 2 + 1) * 32 + kp) * BROW + h;

    float w1 = c1w[(h * EE + e) * 3 + k];
    __nv_bfloat16 h1 = __float2bfloat16(w1);
    g_B1[dhi] = h1;
    g_B1[dlo] = __float2bfloat16(w1 - __bfloat162float(h1));

    float w2 = c2w[(h * EE + e) * 3 + k];
    __nv_bfloat16 h2 = __float2bfloat16(w2);
    g_B2[dhi] = h2;
    g_B2[dlo] = __float2bfloat16(w2 - __bfloat162float(h2));
}

// ---------------------------------------------------------------------------
// conv-as-GEMM via mma.sync bf16 (3x split), fused LN epilogue.
// 512 threads: warp grid 4(M) x 4(N), warp tile 32x64.
// mode 0: outH = relu(LN(conv+bias))                   fp32 [M,256]
// mode 1: outDur = relu(relu(LN(conv+bias)).lw + lb)   fp32 [M]
// ---------------------------------------------------------------------------
__global__ void __launch_bounds__(NT, 1)
conv_mma(const float* __restrict__ X, const __nv_bfloat16* __restrict__ WB,
         const float* __restrict__ bias, const float* __restrict__ gamma,
         const float* __restrict__ beta, const float* __restrict__ lw,
         const float* __restrict__ lb, float* __restrict__ outH,
         float* __restrict__ outDur, int mode)
{
    extern __shared__ char smem[];
    const int tid = threadIdx.x, lane = tid & 31, wid = tid >> 5;
    const int wm = wid >> 2, wn = wid & 3;       // 4 (M) x 4 (N) warps
    uint32_t sb;
    asm("{ .reg .u64 t; cvta.to.shared.u64 t, %1; cvt.u32.u64 %0, t; }"
        : "=r"(sb) : "l"(smem));

    // params into smem: bias @0, gamma @256, beta @512, lw @768 (floats)
    float* smf = (float*)smem;
    if (tid < 256) {
        smf[tid]       = bias[tid];
        smf[256 + tid] = gamma[tid];
        smf[512 + tid] = beta[tid];
        smf[768 + tid] = lw[tid];
    }

    const int m0 = blockIdx.x * 128;
    const float* xb = X + (m0 >> 10) * (LL * EE);
    const int rowA = tid >> 2, q = tid & 3;      // 4 threads per A row, 8 floats each
    const int lg = (m0 & (LL - 1)) + rowA;
    const int abase0 = (lg - 1) * EE + q * 8;

    float d[2][8][4];
#pragma unroll
    for (int i = 0; i < 2; i++)
#pragma unroll
        for (int j = 0; j < 8; j++)
#pragma unroll
            for (int t = 0; t < 4; t++) d[i][j][t] = 0.f;

    const uint32_t laneA = (uint32_t)((lane & 7) + ((lane >> 3) & 1) * 8) * ASTR
                         + ((lane >> 4) & 1) * 16;
    const uint32_t laneB = (uint32_t)((lane & 7) + ((lane >> 3) & 1) * 8) * BSTR
                         + ((lane >> 4) & 1) * 16;

    float4 xr[2];

    auto loadX = [&](int c) {
        int base = abase0 + c * CHK;
        bool valid = (base >= 0) && (base + 8 <= LL * EE);
        xr[0] = valid ? *reinterpret_cast<const float4*>(xb + base)
                      : make_float4(0.f, 0.f, 0.f, 0.f);
        xr[1] = valid ? *reinterpret_cast<const float4*>(xb + base + 4)
                      : make_float4(0.f, 0.f, 0.f, 0.f);
    };

    auto cpB = [&](int c, int buf) {
        const char* src = (const char*)(WB + (size_t)c * BCH);
        uint32_t dst = sb + SM_STAGE + (uint32_t)buf * STAGE_SZ + B_HI;
#pragma unroll
        for (int j = 0; j < 4; j++) {
            uint32_t u = tid + NT * j;
            asm volatile("cp.async.cg.shared.global [%0], [%1], 16;"
                :: "r"(dst + u * 16), "l"(src + (size_t)u * 16) : "memory");
        }
        uint32_t u = tid + 2048;
        if (u < 2112)
            asm volatile("cp.async.cg.shared.global [%0], [%1], 16;"
                :: "r"(dst + u * 16), "l"(src + (size_t)u * 16) : "memory");
        asm volatile("cp.async.commit_group;" ::: "memory");
    };

    auto cvtSTS = [&](int buf) {
        uint32_t hw[4], lwr[4];
#pragma unroll
        for (int i = 0; i < 2; i++) {
            float4 v = xr[i];
            hw[2 * i]     = pack_bf2(v.x, v.y);
            hw[2 * i + 1] = pack_bf2(v.z, v.w);
            float rx = v.x - __bfloat162float(__float2bfloat16(v.x));
            float ry = v.y - __bfloat162float(__float2bfloat16(v.y));
            float rz = v.z - __bfloat162float(__float2bfloat16(v.z));
            float rw = v.w - __bfloat162float(__float2bfloat16(v.w));
            lwr[2 * i]     = pack_bf2(rx, ry);
            lwr[2 * i + 1] = pack_bf2(rz, rw);
        }
        char* st = smem + SM_STAGE + buf * STAGE_SZ;
        uint32_t ao = (uint32_t)rowA * ASTR + q * 16;
        *reinterpret_cast<uint4*>(st + A_HI + ao) =
            make_uint4(hw[0], hw[1], hw[2], hw[3]);
        *reinterpret_cast<uint4*>(st + A_LO + ao) =
            make_uint4(lwr[0], lwr[1], lwr[2], lwr[3]);
    };

    // Fragment-reuse MMA: per k16 slice load Ahi,Bhi,Blo once, Alo reload
    auto do_mma = [&](uint32_t stg) {
#pragma unroll
        for (int kb2 = 0; kb2 < 2; kb2++) {
            uint32_t af[2][4], bh[8][2], bl[8][2];
#pragma unroll
            for (int mf = 0; mf < 2; mf++)
                ldsm4(af[mf], stg + A_HI +
                      (uint32_t)(wm * 32 + mf * 16) * ASTR + kb2 * 32 + laneA);
#pragma unroll
            for (int t = 0; t < 4; t++) {
                uint32_t r[4];
                ldsm4t(r, stg + B_HI + (uint32_t)kb2 * 16 * BSTR +
                       (uint32_t)(wn * 64 + t * 16) * 2 + laneB);
                bh[2 * t][0] = r[0]; bh[2 * t][1] = r[1];
                bh[2 * t + 1][0] = r[2]; bh[2 * t + 1][1] = r[3];
            }
#pragma unroll
            for (int mf = 0; mf < 2; mf++)
#pragma unroll
                for (int nf = 0; nf < 8; nf++)
                    mma_bf16(d[mf][nf], af[mf], bh[nf]);
#pragma unroll
            for (int t = 0; t < 4; t++) {
                uint32_t r[4];
                ldsm4t(r, stg + B_LO + (uint32_t)kb2 * 16 * BSTR +
                       (uint32_t)(wn * 64 + t * 16) * 2 + laneB);
                bl[2 * t][0] = r[0]; bl[2 * t][1] = r[1];
                bl[2 * t + 1][0] = r[2]; bl[2 * t + 1][1] = r[3];
            }
#pragma unroll
            for (int mf = 0; mf < 2; mf++)
#pragma unroll
                for (int nf = 0; nf < 8; nf++)
                    mma_bf16(d[mf][nf], af[mf], bl[nf]);
#pragma unroll
            for (int mf = 0; mf < 2; mf++)
                ldsm4(af[mf], stg + A_LO +
                      (uint32_t)(wm * 32 + mf * 16) * ASTR + kb2 * 32 + laneA);
#pragma unroll
            for (int mf = 0; mf < 2; mf++)
#pragma unroll
                for (int nf = 0; nf < 8; nf++)
                    mma_bf16(d[mf][nf], af[mf], bh[nf]);
        }
    };

    // prologue: 2 cp.async groups in flight, A(0) converted
    loadX(0);
    cpB(0, 0);
    cvtSTS(0);
    loadX(1);
    cpB(1, 1);

    for (int c = 0; c < NCH; c++) {
        if (c < NCH - 2)
            asm volatile("cp.async.wait_group 1;" ::: "memory");
        else
            asm volatile("cp.async.wait_group 0;" ::: "memory");
        __syncthreads();
        if (c + 2 < NCH) cpB(c + 2, (c + 2) % 3);
        if (c + 1 < NCH) cvtSTS((c + 1) % 3);
        if (c + 2 < NCH) loadX(c + 2);
        do_mma(sb + SM_STAGE + (uint32_t)(c % 3) * STAGE_SZ);
    }

    // ------- epilogue: acc(+bias) -> smem tile -> per-row LN -------
    __syncthreads();
    float* tile = (float*)(smem + SM_STAGE);
#pragma unroll
    for (int mf = 0; mf < 2; mf++) {
        int r0 = wm * 32 + mf * 16 + (lane >> 2);
#pragma unroll
        for (int nf = 0; nf < 8; nf++) {
            int cc = wn * 64 + nf * 8 + (lane & 3) * 2;
            float b0 = smf[cc], b1 = smf[cc + 1];
            *reinterpret_cast<float2*>(tile + r0 * EPI_STRIDE + cc) =
                make_float2(d[mf][nf][0] + b0, d[mf][nf][1] + b1);
            *reinterpret_cast<float2*>(tile + (r0 + 8) * EPI_STRIDE + cc) =
                make_float2(d[mf][nf][2] + b0, d[mf][nf][3] + b1);
        }
    }
    __syncthreads();

    {
        int r = tid >> 2, qq = tid & 3;          // 4 threads per row, 64 floats each
        const float4* row =
            (const float4*)(tile + r * EPI_STRIDE + qq * 64);
        float sum = 0.f, ss = 0.f;
#pragma unroll
        for (int i = 0; i < 16; i++) {
            float4 v = row[i];
            sum += v.x + v.y + v.z + v.w;
            ss = fmaf(v.x, v.x, ss); ss = fmaf(v.y, v.y, ss);
            ss = fmaf(v.z, v.z, ss); ss = fmaf(v.w, v.w, ss);
        }
        sum += __shfl_xor_sync(0xffffffffu, sum, 1);
        ss  += __shfl_xor_sync(0xffffffffu, ss, 1);
        sum += __shfl_xor_sync(0xffffffffu, sum, 2);
        ss  += __shfl_xor_sync(0xffffffffu, ss, 2);
        float mu  = sum * (1.f / 256.f);
        float inv = rsqrtf(ss * (1.f / 256.f) - mu * mu + 1e-5f);
        const float4* sG  = (const float4*)(smf + 256 + qq * 64);
        const float4* sBe = (const float4*)(smf + 512 + qq * 64);

        if (mode == 0) {
            float* op = outH + (size_t)(m0 + r) * HH + qq * 64;
#pragma unroll
            for (int i = 0; i < 16; i++) {
                float4 v = row[i], g = sG[i], be = sBe[i], y;
                y.x = fmaxf(fmaf((v.x - mu) * inv, g.x, be.x), 0.f);
                y.y = fmaxf(fmaf((v.y - mu) * inv, g.y, be.y), 0.f);
                y.z = fmaxf(fmaf((v.z - mu) * inv, g.z, be.z), 0.f);
                y.w = fmaxf(fmaf((v.w - mu) * inv, g.w, be.w), 0.f);
                reinterpret_cast<float4*>(op)[i] = y;
            }
        } else {
            const float4* sLw = (const float4*)(smf + 768 + qq * 64);
            float dot = 0.f;
#pragma unroll
            for (int i = 0; i < 16; i++) {
                float4 v = row[i], g = sG[i], be = sBe[i], w = sLw[i];
                dot = fmaf(fmaxf(fmaf((v.x - mu) * inv, g.x, be.x), 0.f), w.x, dot);
                dot = fmaf(fmaxf(fmaf((v.y - mu) * inv, g.y, be.y), 0.f), w.y, dot);
                dot = fmaf(fmaxf(fmaf((v.z - mu) * inv, g.z, be.z), 0.f), w.z, dot);
                dot = fmaf(fmaxf(fmaf((v.w - mu) * inv, g.w, be.w), 0.f), w.w, dot);
            }
            dot += __shfl_xor_sync(0xffffffffu, dot, 1);
            dot += __shfl_xor_sync(0xffffffffu, dot, 2);
            if (qq == 0) outDur[m0 + r] = fmaxf(dot + lb[0], 0.f);
        }
    }
}

// ---------------------------------------------------------------------------
// Per-batch cumsum of target + searchsorted(right) -> g_idx[b,t] (-1 = zero)
// ---------------------------------------------------------------------------
__global__ void scan_idx(const int* __restrict__ target) {
    __shared__ int cum[LL];
    __shared__ int ps[256];
    int b = blockIdx.x;
    int tid = threadIdx.x;
    const int* tb = target + b * LL;
    int v[4], s = 0;
#pragma unroll
    for (int i = 0; i < 4; i++) { v[i] = tb[tid * 4 + i]; s += v[i]; }
    ps[tid] = s;
    __syncthreads();
    for (int o = 1; o < 256; o <<= 1) {
        int t = (tid >= o) ? ps[tid - o] : 0;
        __syncthreads();
        ps[tid] += t;
        __syncthreads();
    }
    int run = ps[tid] - s;
#pragma unroll
    for (int i = 0; i < 4; i++) { run += v[i]; cum[tid * 4 + i] = run; }
    __syncthreads();
    int total = cum[LL - 1];
    for (int t = tid; t < TT; t += 256) {
        int r = -1;
        if (t < total) {
            int lo = 0, hi = LL;
            while (lo < hi) {
                int mid = (lo + hi) >> 1;
                if (cum[mid] <= t) lo = mid + 1; else hi = mid;
            }
            r = lo < (LL - 1) ? lo : (LL - 1);
        }
        g_idx[b * TT + t] = r;
    }
}

// ---------------------------------------------------------------------------
// Gather/zero-fill: out[b,t,:] = (idx>=0) ? x[b,idx,:] : 0
// ---------------------------------------------------------------------------
__global__ void copy_out(const float* __restrict__ X, float* __restrict__ out) {
    int tid  = threadIdx.x;
    int rt   = blockIdx.x * 4 + (tid >> 6);
    int lane = tid & 63;
    int b = rt >> 13;
    int j = g_idx[rt];
    float4 val = make_float4(0.f, 0.f, 0.f, 0.f);
    if (j >= 0)
        val = *reinterpret_cast<const float4*>(X + (b * LL + j) * EE + lane * 4);
    *reinterpret_cast<float4*>(out + (size_t)rt * EE + lane * 4) = val;
}

// ---------------------------------------------------------------------------
extern "C" void kernel_launch(void* const* d_in, const int* in_sizes, int n_in,
                              void* d_out, int out_size) {
    const float* x      = (const float*)d_in[0];
    const int*   target = (const int*)  d_in[1];
    const float* c1w = (const float*)d_in[3];
    const float* c1b = (const float*)d_in[4];
    const float* g1  = (const float*)d_in[5];
    const float* b1  = (const float*)d_in[6];
    const float* c2w = (const float*)d_in[7];
    const float* c2b = (const float*)d_in[8];
    const float* g2  = (const float*)d_in[9];
    const float* b2  = (const float*)d_in[10];
    const float* lw  = (const float*)d_in[11];
    const float* lb  = (const float*)d_in[12];

    float* out = (float*)d_out;
    float* dur = out + OUT_OFF;

    float* H1;
    __nv_bfloat16 *B1, *B2;
    cudaGetSymbolAddress((void**)&H1, g_H1);
    cudaGetSymbolAddress((void**)&B1, g_B1);
    cudaGetSymbolAddress((void**)&B2, g_B2);

    cudaFuncSetAttribute(conv_mma, cudaFuncAttributeMaxDynamicSharedMemorySize,
                         SMEM_BYTES);

    // Side stream + events for fork/join inside graph capture.
    static cudaStream_t s_side = nullptr;
    static cudaEvent_t  ev_fork = nullptr, ev_join = nullptr;
    if (s_side == nullptr) {
        cudaStreamCreateWithFlags(&s_side, cudaStreamNonBlocking);
        cudaEventCreateWithFlags(&ev_fork, cudaEventDisableTiming);
        cudaEventCreateWithFlags(&ev_join, cudaEventDisableTiming);
    }

    // fork: regulate path (scan+gather) is independent of the conv path
    cudaEventRecord(ev_fork, 0);
    cudaStreamWaitEvent(s_side, ev_fork, 0);

    scan_idx<<<BB, 256, 0, s_side>>>(target);
    copy_out<<<(BB * TT) / 4, 256, 0, s_side>>>(x, out);
    cudaEventRecord(ev_join, s_side);

    // main: duration predictor
    prep_weights<<<(HH * KD + 255) / 256, 256>>>(c1w, c2w);
    conv_mma<<<MM / 128, NT, SMEM_BYTES>>>(x, B1, c1b, g1, b1, lw, lb,
                                           H1, nullptr, 0);
    conv_mma<<<MM / 128, NT, SMEM_BYTES>>>(H1, B2, c2b, g2, b2, lw, lb,
                                           nullptr, dur, 1);

    // join
    cudaStreamWaitEvent(0, ev_join, 0);
}

// round 9
// speedup vs baseline: 1.3254x; 1.3254x over previous
#include <cuda_runtime.h>
#include <cuda_fp16.h>
#include <cstdint>

// Problem constants
#define BB 32
#define LL 1024
#define EE 256
#define HH 256
#define TT 8192
#define KD 768                  // 3*256 im2col contraction
#define MM (BB*LL)              // 32768 rows
#define OUT_OFF (BB*TT*EE)      // duration follows output
#define NCH 24                  // K chunks of 32
#define CHK 32

// Weight blocks: per conv [NCH][32 k][264 n] fp16 (264 = 256 + pad)
#define BROW 264
#define BCH  (32*BROW)          // 8448 elems / chunk (fp16 hi only)

__device__ float g_H1[MM*HH];
__device__ __align__(16) __half g_B1[NCH*BCH];
__device__ __align__(16) __half g_B2[NCH*BCH];
__device__ int g_idx[BB*TT];

// SMEM layout (dynamic): params [0,4096), 3 stages from 4096; epilogue reuses stages
#define SM_STAGE 4096
#define A_HI 0
#define A_LO 10240
#define B_HI 20480
#define STAGE_SZ 37376          // A_hi 10K + A_lo 10K + B_hi 16.5K
#define ASTR 80                 // A row stride bytes (32 fp16 + pad)
#define BSTR 528                // B row stride bytes (264 fp16)
#define EPI_STRIDE 264          // epilogue fp32 tile row stride (floats)
#define SMEM_BYTES (4096 + 128*EPI_STRIDE*4)   // 139264 (> 4096+3*STAGE_SZ=116224)

__device__ __forceinline__ void ldsm4(uint32_t* r, uint32_t a) {
    asm volatile("ldmatrix.sync.aligned.m8n8.x4.shared.b16 {%0,%1,%2,%3}, [%4];"
        : "=r"(r[0]), "=r"(r[1]), "=r"(r[2]), "=r"(r[3]) : "r"(a));
}
__device__ __forceinline__ void ldsm4t(uint32_t* r, uint32_t a) {
    asm volatile("ldmatrix.sync.aligned.m8n8.x4.trans.shared.b16 {%0,%1,%2,%3}, [%4];"
        : "=r"(r[0]), "=r"(r[1]), "=r"(r[2]), "=r"(r[3]) : "r"(a));
}
__device__ __forceinline__ void mma_f16(float* d, const uint32_t* a, const uint32_t* b) {
    asm volatile(
        "mma.sync.aligned.m16n8k16.row.col.f32.f16.f16.f32 "
        "{%0,%1,%2,%3}, {%4,%5,%6,%7}, {%8,%9}, {%0,%1,%2,%3};"
        : "+f"(d[0]), "+f"(d[1]), "+f"(d[2]), "+f"(d[3])
        : "r"(a[0]), "r"(a[1]), "r"(a[2]), "r"(a[3]), "r"(b[0]), "r"(b[1]));
}
__device__ __forceinline__ uint32_t pack_h2(float x, float y) {
    __half2 h = __floats2half2_rn(x, y);
    return *reinterpret_cast<uint32_t*>(&h);
}

// ---------------------------------------------------------------------------
// Weight prep: [H,E,K] fp32 -> fp16 in [chunk][k'][n=h] padded rows
// ---------------------------------------------------------------------------
__global__ void prep_weights(const float* __restrict__ c1w,
                             const float* __restrict__ c2w) {
    int i = blockIdx.x * blockDim.x + threadIdx.x;
    if (i >= HH * KD) return;
    int h = i / KD, kk = i % KD;
    int k = kk / EE, e = kk % EE;
    int c = kk >> 5, kp = kk & 31;
    size_t d = ((size_t)c * 32 + kp) * BROW + h;
    g_B1[d] = __float2half_rn(c1w[(h * EE + e) * 3 + k]);
    g_B2[d] = __float2half_rn(c2w[(h * EE + e) * 3 + k]);
}

// ---------------------------------------------------------------------------
// conv-as-GEMM via mma.sync fp16, 2-pass A split (A = Ahi+Alo, B = fp16(W)).
// 256 threads: warp grid 2(M) x 4(N), warp tile 64x64.
// mode 0: outH = relu(LN(conv+bias))                   fp32 [M,256]
// mode 1: outDur = relu(relu(LN(conv+bias)).lw + lb)   fp32 [M]
// ---------------------------------------------------------------------------
__global__ void __launch_bounds__(256, 1)
conv_mma(const float* __restrict__ X, const __half* __restrict__ WB,
         const float* __restrict__ bias, const float* __restrict__ gamma,
         const float* __restrict__ beta, const float* __restrict__ lw,
         const float* __restrict__ lb, float* __restrict__ outH,
         float* __restrict__ outDur, int mode)
{
    extern __shared__ char smem[];
    const int tid = threadIdx.x, lane = tid & 31, wid = tid >> 5;
    const int wm = wid >> 2, wn = wid & 3;       // 2 (M) x 4 (N) warps
    uint32_t sb;
    asm("{ .reg .u64 t; cvta.to.shared.u64 t, %1; cvt.u32.u64 %0, t; }"
        : "=r"(sb) : "l"(smem));

    // params into smem: bias @0, gamma @256, beta @512, lw @768 (floats)
    float* smf = (float*)smem;
    smf[tid]       = bias[tid];
    smf[256 + tid] = gamma[tid];
    smf[512 + tid] = beta[tid];
    smf[768 + tid] = lw[tid];

    const int m0 = blockIdx.x * 128;
    const float* xb = X + (m0 >> 10) * (LL * EE);
    const int rowA = tid >> 1, half = tid & 1;
    const int lg = (m0 & (LL - 1)) + rowA;
    const int abase0 = (lg - 1) * EE + half * 16;

    float d[4][8][4];
#pragma unroll
    for (int i = 0; i < 4; i++)
#pragma unroll
        for (int j = 0; j < 8; j++)
#pragma unroll
            for (int q = 0; q < 4; q++) d[i][j][q] = 0.f;

    const uint32_t laneA = (uint32_t)((lane & 7) + ((lane >> 3) & 1) * 8) * ASTR
                         + ((lane >> 4) & 1) * 16;
    const uint32_t laneB = (uint32_t)((lane & 7) + ((lane >> 3) & 1) * 8) * BSTR
                         + ((lane >> 4) & 1) * 16;

    float4 xr[4];

    auto loadX = [&](int c) {
        int base = abase0 + c * CHK;
        bool valid = (base >= 0) && (base + 16 <= LL * EE);
#pragma unroll
        for (int i = 0; i < 4; i++)
            xr[i] = valid ? *reinterpret_cast<const float4*>(xb + base + i * 4)
                          : make_float4(0.f, 0.f, 0.f, 0.f);
    };

    auto cpB = [&](int c, int buf) {
        const char* src = (const char*)(WB + (size_t)c * BCH);
        uint32_t dst = sb + SM_STAGE + (uint32_t)buf * STAGE_SZ + B_HI;
#pragma unroll
        for (int j = 0; j < 4; j++) {
            uint32_t u = tid + 256 * j;
            asm volatile("cp.async.cg.shared.global [%0], [%1], 16;"
                :: "r"(dst + u * 16), "l"(src + (size_t)u * 16) : "memory");
        }
        uint32_t u = tid + 1024;
        if (u < 1056)
            asm volatile("cp.async.cg.shared.global [%0], [%1], 16;"
                :: "r"(dst + u * 16), "l"(src + (size_t)u * 16) : "memory");
        asm volatile("cp.async.commit_group;" ::: "memory");
    };

    auto cvtSTS = [&](int buf) {
        uint32_t hw[8], lwr[8];
#pragma unroll
        for (int i = 0; i < 4; i++) {
            float4 v = xr[i];
            hw[2 * i]     = pack_h2(v.x, v.y);
            hw[2 * i + 1] = pack_h2(v.z, v.w);
            float rx = v.x - __half2float(__float2half_rn(v.x));
            float ry = v.y - __half2float(__float2half_rn(v.y));
            float rz = v.z - __half2float(__float2half_rn(v.z));
            float rw = v.w - __half2float(__float2half_rn(v.w));
            lwr[2 * i]     = pack_h2(rx, ry);
            lwr[2 * i + 1] = pack_h2(rz, rw);
        }
        char* st = smem + SM_STAGE + buf * STAGE_SZ;
        uint32_t ao = (uint32_t)rowA * ASTR + half * 32;
        *reinterpret_cast<uint4*>(st + A_HI + ao) =
            make_uint4(hw[0], hw[1], hw[2], hw[3]);
        *reinterpret_cast<uint4*>(st + A_HI + ao + 16) =
            make_uint4(hw[4], hw[5], hw[6], hw[7]);
        *reinterpret_cast<uint4*>(st + A_LO + ao) =
            make_uint4(lwr[0], lwr[1], lwr[2], lwr[3]);
        *reinterpret_cast<uint4*>(st + A_LO + ao + 16) =
            make_uint4(lwr[4], lwr[5], lwr[6], lwr[7]);
    };

    // 2-pass MMA per k16 slice: Ahi*Bh, then Alo*Bh (B frags reused)
    auto do_mma = [&](uint32_t stg) {
#pragma unroll
        for (int kb2 = 0; kb2 < 2; kb2++) {
            uint32_t af[4][4], bh[8][2];
#pragma unroll
            for (int mf = 0; mf < 4; mf++)
                ldsm4(af[mf], stg + A_HI +
                      (uint32_t)(wm * 64 + mf * 16) * ASTR + kb2 * 32 + laneA);
#pragma unroll
            for (int t = 0; t < 4; t++) {
                uint32_t r[4];
                ldsm4t(r, stg + B_HI + (uint32_t)kb2 * 16 * BSTR +
                       (uint32_t)(wn * 64 + t * 16) * 2 + laneB);
                bh[2 * t][0] = r[0]; bh[2 * t][1] = r[1];
                bh[2 * t + 1][0] = r[2]; bh[2 * t + 1][1] = r[3];
            }
#pragma unroll
            for (int mf = 0; mf < 4; mf++)
#pragma unroll
                for (int nf = 0; nf < 8; nf++)
                    mma_f16(d[mf][nf], af[mf], bh[nf]);
#pragma unroll
            for (int mf = 0; mf < 4; mf++)
                ldsm4(af[mf], stg + A_LO +
                      (uint32_t)(wm * 64 + mf * 16) * ASTR + kb2 * 32 + laneA);
#pragma unroll
            for (int mf = 0; mf < 4; mf++)
#pragma unroll
                for (int nf = 0; nf < 8; nf++)
                    mma_f16(d[mf][nf], af[mf], bh[nf]);
        }
    };

    // prologue: 2 cp.async groups in flight, A(0) converted
    loadX(0);
    cpB(0, 0);
    cvtSTS(0);
    loadX(1);
    cpB(1, 1);

    for (int c = 0; c < NCH; c++) {
        if (c < NCH - 2)
            asm volatile("cp.async.wait_group 1;" ::: "memory");
        else
            asm volatile("cp.async.wait_group 0;" ::: "memory");
        __syncthreads();
        if (c + 2 < NCH) cpB(c + 2, (c + 2) % 3);
        if (c + 1 < NCH) cvtSTS((c + 1) % 3);
        if (c + 2 < NCH) loadX(c + 2);
        do_mma(sb + SM_STAGE + (uint32_t)(c % 3) * STAGE_SZ);
    }

    // ------- epilogue: acc(+bias) -> smem tile -> per-row LN -------
    __syncthreads();
    float* tile = (float*)(smem + SM_STAGE);
#pragma unroll
    for (int mf = 0; mf < 4; mf++) {
        int r0 = wm * 64 + mf * 16 + (lane >> 2);
#pragma unroll
        for (int nf = 0; nf < 8; nf++) {
            int cc = wn * 64 + nf * 8 + (lane & 3) * 2;
            float b0 = smf[cc], b1 = smf[cc + 1];
            *reinterpret_cast<float2*>(tile + r0 * EPI_STRIDE + cc) =
                make_float2(d[mf][nf][0] + b0, d[mf][nf][1] + b1);
            *reinterpret_cast<float2*>(tile + (r0 + 8) * EPI_STRIDE + cc) =
                make_float2(d[mf][nf][2] + b0, d[mf][nf][3] + b1);
        }
    }
    __syncthreads();

    {
        int r = tid >> 1, h2 = tid & 1;
        const float4* row =
            (const float4*)(tile + r * EPI_STRIDE + h2 * 128);
        float sum = 0.f, ss = 0.f;
#pragma unroll
        for (int i = 0; i < 32; i++) {
            float4 v = row[i];
            sum += v.x + v.y + v.z + v.w;
            ss = fmaf(v.x, v.x, ss); ss = fmaf(v.y, v.y, ss);
            ss = fmaf(v.z, v.z, ss); ss = fmaf(v.w, v.w, ss);
        }
        sum += __shfl_xor_sync(0xffffffffu, sum, 1);
        ss  += __shfl_xor_sync(0xffffffffu, ss, 1);
        float mu  = sum * (1.f / 256.f);
        float inv = rsqrtf(ss * (1.f / 256.f) - mu * mu + 1e-5f);
        const float4* sG  = (const float4*)(smf + 256 + h2 * 128);
        const float4* sBe = (const float4*)(smf + 512 + h2 * 128);

        if (mode == 0) {
            float* op = outH + (size_t)(m0 + r) * HH + h2 * 128;
#pragma unroll
            for (int i = 0; i < 32; i++) {
                float4 v = row[i], g = sG[i], be = sBe[i], y;
                y.x = fmaxf(fmaf((v.x - mu) * inv, g.x, be.x), 0.f);
                y.y = fmaxf(fmaf((v.y - mu) * inv, g.y, be.y), 0.f);
                y.z = fmaxf(fmaf((v.z - mu) * inv, g.z, be.z), 0.f);
                y.w = fmaxf(fmaf((v.w - mu) * inv, g.w, be.w), 0.f);
                reinterpret_cast<float4*>(op)[i] = y;
            }
        } else {
            const float4* sLw = (const float4*)(smf + 768 + h2 * 128);
            float dot = 0.f;
#pragma unroll
            for (int i = 0; i < 32; i++) {
                float4 v = row[i], g = sG[i], be = sBe[i], w = sLw[i];
                dot = fmaf(fmaxf(fmaf((v.x - mu) * inv, g.x, be.x), 0.f), w.x, dot);
                dot = fmaf(fmaxf(fmaf((v.y - mu) * inv, g.y, be.y), 0.f), w.y, dot);
                dot = fmaf(fmaxf(fmaf((v.z - mu) * inv, g.z, be.z), 0.f), w.z, dot);
                dot = fmaf(fmaxf(fmaf((v.w - mu) * inv, g.w, be.w), 0.f), w.w, dot);
            }
            dot += __shfl_xor_sync(0xffffffffu, dot, 1);
            if (h2 == 0) outDur[m0 + r] = fmaxf(dot + lb[0], 0.f);
        }
    }
}

// ---------------------------------------------------------------------------
// Per-batch cumsum of target + searchsorted(right) -> g_idx[b,t] (-1 = zero)
// ---------------------------------------------------------------------------
__global__ void scan_idx(const int* __restrict__ target) {
    __shared__ int cum[LL];
    __shared__ int ps[256];
    int b = blockIdx.x;
    int tid = threadIdx.x;
    const int* tb = target + b * LL;
    int v[4], s = 0;
#pragma unroll
    for (int i = 0; i < 4; i++) { v[i] = tb[tid * 4 + i]; s += v[i]; }
    ps[tid] = s;
    __syncthreads();
    for (int o = 1; o < 256; o <<= 1) {
        int t = (tid >= o) ? ps[tid - o] : 0;
        __syncthreads();
        ps[tid] += t;
        __syncthreads();
    }
    int run = ps[tid] - s;
#pragma unroll
    for (int i = 0; i < 4; i++) { run += v[i]; cum[tid * 4 + i] = run; }
    __syncthreads();
    int total = cum[LL - 1];
    for (int t = tid; t < TT; t += 256) {
        int r = -1;
        if (t < total) {
            int lo = 0, hi = LL;
            while (lo < hi) {
                int mid = (lo + hi) >> 1;
                if (cum[mid] <= t) lo = mid + 1; else hi = mid;
            }
            r = lo < (LL - 1) ? lo : (LL - 1);
        }
        g_idx[b * TT + t] = r;
    }
}

// ---------------------------------------------------------------------------
// Gather/zero-fill: out[b,t,:] = (idx>=0) ? x[b,idx,:] : 0
// ---------------------------------------------------------------------------
__global__ void copy_out(const float* __restrict__ X, float* __restrict__ out) {
    int tid  = threadIdx.x;
    int rt   = blockIdx.x * 4 + (tid >> 6);
    int lane = tid & 63;
    int b = rt >> 13;
    int j = g_idx[rt];
    float4 val = make_float4(0.f, 0.f, 0.f, 0.f);
    if (j >= 0)
        val = *reinterpret_cast<const float4*>(X + (b * LL + j) * EE + lane * 4);
    *reinterpret_cast<float4*>(out + (size_t)rt * EE + lane * 4) = val;
}

// ---------------------------------------------------------------------------
extern "C" void kernel_launch(void* const* d_in, const int* in_sizes, int n_in,
                              void* d_out, int out_size) {
    const float* x      = (const float*)d_in[0];
    const int*   target = (const int*)  d_in[1];
    const float* c1w = (const float*)d_in[3];
    const float* c1b = (const float*)d_in[4];
    const float* g1  = (const float*)d_in[5];
    const float* b1  = (const float*)d_in[6];
    const float* c2w = (const float*)d_in[7];
    const float* c2b = (const float*)d_in[8];
    const float* g2  = (const float*)d_in[9];
    const float* b2  = (const float*)d_in[10];
    const float* lw  = (const float*)d_in[11];
    const float* lb  = (const float*)d_in[12];

    float* out = (float*)d_out;
    float* dur = out + OUT_OFF;

    float* H1;
    __half *B1, *B2;
    cudaGetSymbolAddress((void**)&H1, g_H1);
    cudaGetSymbolAddress((void**)&B1, g_B1);
    cudaGetSymbolAddress((void**)&B2, g_B2);

    cudaFuncSetAttribute(conv_mma, cudaFuncAttributeMaxDynamicSharedMemorySize,
                         SMEM_BYTES);

    // Side stream + events for fork/join inside graph capture.
    static cudaStream_t s_side = nullptr;
    static cudaEvent_t  ev_fork = nullptr, ev_join = nullptr;
    if (s_side == nullptr) {
        cudaStreamCreateWithFlags(&s_side, cudaStreamNonBlocking);
        cudaEventCreateWithFlags(&ev_fork, cudaEventDisableTiming);
        cudaEventCreateWithFlags(&ev_join, cudaEventDisableTiming);
    }

    // fork: regulate path (scan+gather) is independent of the conv path
    cudaEventRecord(ev_fork, 0);
    cudaStreamWaitEvent(s_side, ev_fork, 0);

    scan_idx<<<BB, 256, 0, s_side>>>(target);
    copy_out<<<(BB * TT) / 4, 256, 0, s_side>>>(x, out);
    cudaEventRecord(ev_join, s_side);

    // main: duration predictor
    prep_weights<<<(HH * KD + 255) / 256, 256>>>(c1w, c2w);
    conv_mma<<<MM / 128, 256, SMEM_BYTES>>>(x, B1, c1b, g1, b1, lw, lb,
                                            H1, nullptr, 0);
    conv_mma<<<MM / 128, 256, SMEM_BYTES>>>(H1, B2, c2b, g2, b2, lw, lb,
                                            nullptr, dur, 1);

    // join
    cudaStreamWaitEvent(0, ev_join, 0);
}